// round 16
// baseline (speedup 1.0000x reference)
#include <cuda_runtime.h>
#include <math.h>

#define N_TIME   8192
#define NBANDS   128
#define THREADS  512
#define NWARPS   (THREADS / 32)     // 16
#define NF4      (N_TIME / 4)       // 2048 float4 per row
#define ITERS    4                  // float4 groups per lane

// MUFU EX2/LG2 via inline PTX (fast approx path).
__device__ __forceinline__ float ex2f(float x) {
    float y;
    asm("ex2.approx.ftz.f32 %0, %1;" : "=f"(y) : "f"(x));
    return y;
}
__device__ __forceinline__ float lg2f(float x) {
    float y;
    asm("lg2.approx.ftz.f32 %0, %1;" : "=f"(y) : "f"(x));
    return y;
}

// Degree-5 Chebyshev fit of ln(1+w) on w in [0, 0.7], evaluated in
// xi = w/0.35 - 1 (monomial form of the Chebyshev series, rho=0.1319).
// Verified abs err <= ~5e-6 at w = {0, 0.35, 0.525, 0.7}.
#define LP_GAMMA 2.857142857f
#define LP_A0 0.3001026f
#define LP_A1 0.2592581f
#define LP_A2 (-0.0335761f)
#define LP_A3 0.00579774f
#define LP_A4 (-0.00121008f)
#define LP_A5 0.000255342f
#define W_GUARD 0.695f

__global__ void __launch_bounds__(THREADS, 2)
mrpcen_kernel(const float* __restrict__ x,
              const float* __restrict__ log_alpha,
              const float* __restrict__ log_delta,
              const float* __restrict__ log_r,
              float* __restrict__ out,
              float4 sv, int nbands)
{
    __shared__ float warp_tot[4][NWARPS];
    __shared__ float warp_excl[4][NWARPS];

    const int row  = blockIdx.x;              // b*F + f
    const int b    = row / nbands;
    const int f    = row % nbands;
    const int lane = threadIdx.x & 31;
    const int warp = threadIdx.x >> 5;

    const float4* __restrict__ xrow4 =
        reinterpret_cast<const float4*>(x) + (size_t)row * NF4;

    const float L2E = 1.4426950408889634f;    // log2(e)
    const float LN2 = 0.6931471805599453f;

    const float m0    = __ldg(x + (size_t)row * N_TIME);   // m[-1] = x[0]
    const float lgd   = __ldg(log_delta + f);              // ln(delta)
    const float alpha = ex2f(L2E * __ldg(log_alpha + f));
    const float rr    = ex2f(L2E * __ldg(log_r + f));
    const float dr    = ex2f(rr * lgd * L2E);              // delta^r
    const float nl2d  = -lgd * L2E;                        // -log2(delta)

    // out = dr*expm1(rr*L), L = ln(1+w):
    //   out = L * (H0 + H1 L + H2 L^2 + H3 L^3),  Hn = dr*rr^(n+1)/(n+1)!
    // (H4 term < 1e-6: dropped)
    const float rr2 = rr * rr;
    const float H0 = dr * rr;
    const float H1 = dr * rr2 * 0.5f;
    const float H2 = dr * rr2 * rr * (1.f / 6.f);
    const float H3 = dr * rr2 * rr2 * (1.f / 24.f);

    // per-rate constants: s, q, A = q^4 (group multiplier), lg2(q), m0/s
    float s[4], q[4], A[4], lg2q[4], m0s[4];
    #pragma unroll
    for (int t = 0; t < 4; t++) {
        s[t] = (t == 0) ? sv.x : (t == 1) ? sv.y : (t == 2) ? sv.z : sv.w;
        q[t] = 1.0f - s[t];
        float q2 = q[t] * q[t];
        A[t] = q2 * q2;               // q^4 exact
        lg2q[t] = lg2f(q[t]);         // finite: q in (0,1]
        m0s[t]  = __fdividef(m0, s[t]);   // scaled-space initial state
    }

    // ============ ALL SCAN WORK IN SCALED SPACE m' = m/s ============
    // recurrence: m' = x + q*m'

    // ---- phase 1: coalesced loads + per-group affine reduction ----
    float c[4][ITERS];
    #pragma unroll
    for (int i = 0; i < ITERS; i++) {
        const float4 v = __ldg(xrow4 + warp * 128 + i * 32 + lane);
        #pragma unroll
        for (int t = 0; t < 4; t++) {
            float cc = v.x;
            cc = fmaf(q[t], cc, v.y);
            cc = fmaf(q[t], cc, v.z);
            cc = fmaf(q[t], cc, v.w);
            c[t][i] = cc;
        }
    }

    // ---- phase 2: per rate, 4 independent warp scans over lanes ----
    float E[4][ITERS];
    float T[4][ITERS];
    float B[4];
    #pragma unroll
    for (int t = 0; t < 4; t++) {
        float S0 = c[t][0], S1 = c[t][1], S2 = c[t][2], S3 = c[t][3];
        float P = A[t];
        #pragma unroll
        for (int o = 1; o < 32; o <<= 1) {
            float v0 = __shfl_up_sync(0xffffffffu, S0, o);
            float v1 = __shfl_up_sync(0xffffffffu, S1, o);
            float v2 = __shfl_up_sync(0xffffffffu, S2, o);
            float v3 = __shfl_up_sync(0xffffffffu, S3, o);
            if (lane >= o) {
                S0 = fmaf(P, v0, S0); S1 = fmaf(P, v1, S1);
                S2 = fmaf(P, v2, S2); S3 = fmaf(P, v3, S3);
            }
            P *= P;
        }
        B[t] = P;
        E[t][0] = __shfl_up_sync(0xffffffffu, S0, 1);
        E[t][1] = __shfl_up_sync(0xffffffffu, S1, 1);
        E[t][2] = __shfl_up_sync(0xffffffffu, S2, 1);
        E[t][3] = __shfl_up_sync(0xffffffffu, S3, 1);
        if (lane == 0) { E[t][0] = 0.f; E[t][1] = 0.f; E[t][2] = 0.f; E[t][3] = 0.f; }
        T[t][0] = __shfl_sync(0xffffffffu, S0, 31);
        T[t][1] = __shfl_sync(0xffffffffu, S1, 31);
        T[t][2] = __shfl_sync(0xffffffffu, S2, 31);
        T[t][3] = __shfl_sync(0xffffffffu, S3, 31);
        float U = fmaf(P, fmaf(P, fmaf(P, T[t][0], T[t][1]), T[t][2]), T[t][3]);
        if (lane == 0) warp_tot[t][warp] = U;
    }
    __syncthreads();

    // ---- phase 3: block scan over 16 warp totals per rate ----
    if (warp == 0) {
        float W[4], Pq[4];
        #pragma unroll
        for (int t = 0; t < 4; t++) {
            W[t]  = (lane < NWARPS) ? warp_tot[t][lane] : 0.0f;
            float B2 = B[t] * B[t];
            Pq[t] = B2 * B2;          // q^512 (may flush to 0: OK)
        }
        #pragma unroll
        for (int o = 1; o < NWARPS; o <<= 1) {
            #pragma unroll
            for (int t = 0; t < 4; t++) {
                float v = __shfl_up_sync(0xffffffffu, W[t], o);
                if (lane >= o) W[t] = fmaf(Pq[t], v, W[t]);
                Pq[t] *= Pq[t];
            }
        }
        #pragma unroll
        for (int t = 0; t < 4; t++) {
            float Wex = __shfl_up_sync(0xffffffffu, W[t], 1);
            if (lane == 0) Wex = 0.0f;
            if (lane < NWARPS) warp_excl[t][lane] = Wex;
        }
    }
    __syncthreads();

    // ---- collapse carry state ----
    float C0[4][ITERS];
    #pragma unroll
    for (int t = 0; t < 4; t++) {
        const float Bt = B[t];
        const float Dw = ex2f((float)(warp * 512) * lg2q[t]);
        float M0 = fmaf(Dw, m0s[t], warp_excl[t][warp]);
        float M1 = fmaf(Bt, M0, T[t][0]);
        float M2 = fmaf(Bt, M1, T[t][1]);
        float M3 = fmaf(Bt, M2, T[t][2]);
        const float Al = ex2f((float)(lane * 4) * lg2q[t]);
        C0[t][0] = fmaf(Al, M0, E[t][0]);
        C0[t][1] = fmaf(Al, M1, E[t][1]);
        C0[t][2] = fmaf(Al, M2, E[t][2]);
        C0[t][3] = fmaf(Al, M3, E[t][3]);
    }

    const float nalpha = -alpha;

    // ---- phase 4: fused emit, 2-MUFU epilogue with polynomial ln(1+w) ----
    float4* __restrict__ obase = reinterpret_cast<float4*>(out) +
        ((size_t)b * 4 * nbands + f) * NF4;
    const size_t ostride = (size_t)nbands * NF4;

    #pragma unroll
    for (int i = 0; i < ITERS; i++) {
        const int g = warp * 128 + i * 32 + lane;
        const float4 xi4 = __ldg(xrow4 + g);

        #pragma unroll
        for (int tv = 0; tv < 4; tv++) {
            const float st = s[tv];
            const float qt = q[tv];
            float cy = C0[tv][i];

            // MUFU front-end: w_k = x * (EPS+m)^-a / d
            float wv[4];
            #pragma unroll
            for (int k = 0; k < 4; k++) {
                const float xi = (&xi4.x)[k];
                cy = fmaf(qt, cy, xi);                       // scaled EMA
                const float u = fmaf(st, cy, 1e-5f);         // EPS + m
                wv[k] = xi * ex2f(fmaf(nalpha, lg2f(u), nl2d));
            }

            // L_k = ln(1+w_k): degree-5 poly on [0,0.7], exact-MUFU
            // fallback for rare large w (warp-uniform ballot branch)
            float L[4];
            const float wmax = fmaxf(fmaxf(wv[0], wv[1]), fmaxf(wv[2], wv[3]));
            if (__ballot_sync(0xffffffffu, wmax > W_GUARD)) {
                #pragma unroll
                for (int k = 0; k < 4; k++)
                    L[k] = LN2 * lg2f(1.0f + wv[k]);
            } else {
                #pragma unroll
                for (int k = 0; k < 4; k++) {
                    const float xc = fmaf(LP_GAMMA, wv[k], -1.0f);
                    float p = LP_A5;
                    p = fmaf(p, xc, LP_A4);
                    p = fmaf(p, xc, LP_A3);
                    p = fmaf(p, xc, LP_A2);
                    p = fmaf(p, xc, LP_A1);
                    L[k] = fmaf(p, xc, LP_A0);
                }
            }

            // out = L * (H0 + H1 L + H2 L^2 + H3 L^3)  (= dr*expm1(rr*L))
            float4 o4;
            #pragma unroll
            for (int k = 0; k < 4; k++) {
                const float Lv = L[k];
                float pq = fmaf(H3, Lv, H2);
                pq = fmaf(pq, Lv, H1);
                pq = fmaf(pq, Lv, H0);
                (&o4.x)[k] = Lv * pq;
            }
            obase[(size_t)tv * ostride + g] = o4;      // coalesced STG.128
        }
    }
}

extern "C" void kernel_launch(void* const* d_in, const int* in_sizes, int n_in,
                              void* d_out, int out_size)
{
    const float* x  = (const float*)d_in[0];
    const float* la = (const float*)d_in[1];
    const float* ld = (const float*)d_in[2];
    const float* lr = (const float*)d_in[3];
    float* out = (float*)d_out;

    const int nbands = in_sizes[1];                 // 128
    const int rows   = in_sizes[0] / N_TIME;        // B * F = 1024

    // s = (sqrt(1 + 4 t^2) - 1) / (2 t^2), computed in double on host
    const double tvals[4] = {2.0, 8.0, 32.0, 128.0};
    float ss[4];
    for (int i = 0; i < 4; i++) {
        double t = tvals[i];
        ss[i] = (float)((sqrt(1.0 + 4.0 * t * t) - 1.0) / (2.0 * t * t));
    }
    float4 sv = make_float4(ss[0], ss[1], ss[2], ss[3]);

    mrpcen_kernel<<<rows, THREADS>>>(x, la, ld, lr, out, sv, nbands);
}

// round 17
// speedup vs baseline: 1.0890x; 1.0890x over previous
#include <cuda_runtime.h>
#include <math.h>

#define N_TIME   8192
#define NBANDS   128
#define THREADS  512
#define NWARPS   (THREADS / 32)     // 16
#define NF4      (N_TIME / 4)       // 2048 float4 per row
#define ITERS    4                  // float4 groups per lane

// MUFU EX2/LG2 via inline PTX (fast approx path).
__device__ __forceinline__ float ex2f(float x) {
    float y;
    asm("ex2.approx.ftz.f32 %0, %1;" : "=f"(y) : "f"(x));
    return y;
}
__device__ __forceinline__ float lg2f(float x) {
    float y;
    asm("lg2.approx.ftz.f32 %0, %1;" : "=f"(y) : "f"(x));
    return y;
}
// Streaming store (evict-first): output is never re-read.
__device__ __forceinline__ void stcs4(float4* p, float4 v) {
    asm volatile("st.global.cs.v4.f32 [%0], {%1, %2, %3, %4};"
                 :: "l"(p), "f"(v.x), "f"(v.y), "f"(v.z), "f"(v.w)
                 : "memory");
}

__global__ void __launch_bounds__(THREADS, 2)
mrpcen_kernel(const float* __restrict__ x,
              const float* __restrict__ log_alpha,
              const float* __restrict__ log_delta,
              const float* __restrict__ log_r,
              float* __restrict__ out,
              float4 sv, int nbands)
{
    __shared__ float warp_tot[4][NWARPS];
    __shared__ float warp_excl[4][NWARPS];

    const int row  = blockIdx.x;              // b*F + f
    const int b    = row / nbands;
    const int f    = row % nbands;
    const int lane = threadIdx.x & 31;
    const int warp = threadIdx.x >> 5;

    const float4* __restrict__ xrow4 =
        reinterpret_cast<const float4*>(x) + (size_t)row * NF4;

    const float L2E = 1.4426950408889634f;    // log2(e)
    const float LN2 = 0.6931471805599453f;

    const float m0    = __ldg(x + (size_t)row * N_TIME);   // m[-1] = x[0]
    const float lgd   = __ldg(log_delta + f);              // ln(delta)
    const float alpha = ex2f(L2E * __ldg(log_alpha + f));
    const float rr    = ex2f(L2E * __ldg(log_r + f));
    const float dr    = ex2f(rr * lgd * L2E);              // delta^r
    const float nl2d  = -lgd * L2E;                        // -log2(delta)
    const float cr    = rr * LN2;                          // r*ln2

    // out = z' * (G0 + G1 z' + G2 z'^2 + G3 z'^3 + G4 z'^4)
    //   z' = lg2(1 + w),  Gn = dr*cr*cr^n/(n+1)!
    // (4-term tail empirically sufficient: R13-R15 measured rel_err 1.3e-6.)
    const float drcr = dr * cr;
    const float cr2  = cr * cr;
    const float G0   = drcr;
    const float G1   = drcr * cr * 0.5f;
    const float G2   = drcr * cr2 * (1.f / 6.f);
    const float G3   = drcr * cr2 * cr * (1.f / 24.f);
    const float G4   = drcr * cr2 * cr2 * (1.f / 120.f);

    // per-rate constants: s, q, A = q^4 (group multiplier), lg2(q), m0/s
    float s[4], q[4], A[4], lg2q[4], m0s[4];
    #pragma unroll
    for (int t = 0; t < 4; t++) {
        s[t] = (t == 0) ? sv.x : (t == 1) ? sv.y : (t == 2) ? sv.z : sv.w;
        q[t] = 1.0f - s[t];
        float q2 = q[t] * q[t];
        A[t] = q2 * q2;               // q^4 exact
        lg2q[t] = lg2f(q[t]);         // finite: q in (0,1]
        m0s[t]  = __fdividef(m0, s[t]);   // scaled-space initial state
    }

    // ============ ALL SCAN WORK IN SCALED SPACE m' = m/s ============
    // recurrence: m' = x + q*m'

    // ---- phase 1: coalesced loads + per-group affine reduction ----
    float c[4][ITERS];
    #pragma unroll
    for (int i = 0; i < ITERS; i++) {
        const float4 v = __ldg(xrow4 + warp * 128 + i * 32 + lane);
        #pragma unroll
        for (int t = 0; t < 4; t++) {
            float cc = v.x;
            cc = fmaf(q[t], cc, v.y);
            cc = fmaf(q[t], cc, v.z);
            cc = fmaf(q[t], cc, v.w);
            c[t][i] = cc;
        }
    }

    // ---- phase 2: per rate, 4 independent warp scans over lanes ----
    float E[4][ITERS];
    float T[4][ITERS];
    float B[4];
    #pragma unroll
    for (int t = 0; t < 4; t++) {
        float S0 = c[t][0], S1 = c[t][1], S2 = c[t][2], S3 = c[t][3];
        float P = A[t];
        #pragma unroll
        for (int o = 1; o < 32; o <<= 1) {
            float v0 = __shfl_up_sync(0xffffffffu, S0, o);
            float v1 = __shfl_up_sync(0xffffffffu, S1, o);
            float v2 = __shfl_up_sync(0xffffffffu, S2, o);
            float v3 = __shfl_up_sync(0xffffffffu, S3, o);
            if (lane >= o) {
                S0 = fmaf(P, v0, S0); S1 = fmaf(P, v1, S1);
                S2 = fmaf(P, v2, S2); S3 = fmaf(P, v3, S3);
            }
            P *= P;                   // after loop: P = A^32
        }
        B[t] = P;
        E[t][0] = __shfl_up_sync(0xffffffffu, S0, 1);
        E[t][1] = __shfl_up_sync(0xffffffffu, S1, 1);
        E[t][2] = __shfl_up_sync(0xffffffffu, S2, 1);
        E[t][3] = __shfl_up_sync(0xffffffffu, S3, 1);
        if (lane == 0) { E[t][0] = 0.f; E[t][1] = 0.f; E[t][2] = 0.f; E[t][3] = 0.f; }
        T[t][0] = __shfl_sync(0xffffffffu, S0, 31);
        T[t][1] = __shfl_sync(0xffffffffu, S1, 31);
        T[t][2] = __shfl_sync(0xffffffffu, S2, 31);
        T[t][3] = __shfl_sync(0xffffffffu, S3, 31);
        // warp-tile total U = T3 + B*T2 + B^2*T1 + B^3*T0
        float U = fmaf(P, fmaf(P, fmaf(P, T[t][0], T[t][1]), T[t][2]), T[t][3]);
        if (lane == 0) warp_tot[t][warp] = U;
    }
    __syncthreads();

    // ---- phase 3: block scan over 16 warp totals per rate (mult D=B^4) ----
    // Dt = q^512 may underflow to 0 for fast rates; numerically correct.
    if (warp == 0) {
        float W[4], Pq[4];
        #pragma unroll
        for (int t = 0; t < 4; t++) {
            W[t]  = (lane < NWARPS) ? warp_tot[t][lane] : 0.0f;
            float B2 = B[t] * B[t];
            Pq[t] = B2 * B2;          // D = q^512 (may flush to 0: OK)
        }
        #pragma unroll
        for (int o = 1; o < NWARPS; o <<= 1) {
            #pragma unroll
            for (int t = 0; t < 4; t++) {
                float v = __shfl_up_sync(0xffffffffu, W[t], o);
                if (lane >= o) W[t] = fmaf(Pq[t], v, W[t]);
                Pq[t] *= Pq[t];
            }
        }
        #pragma unroll
        for (int t = 0; t < 4; t++) {
            float Wex = __shfl_up_sync(0xffffffffu, W[t], 1);
            if (lane == 0) Wex = 0.0f;
            if (lane < NWARPS) warp_excl[t][lane] = Wex;
        }
    }
    __syncthreads();

    // ---- collapse carry state: C0[t][i] = scaled carry entering my group ----
    float C0[4][ITERS];
    #pragma unroll
    for (int t = 0; t < 4; t++) {
        const float Bt = B[t];
        const float Dw = ex2f((float)(warp * 512) * lg2q[t]);  // q^(512*warp)
        float M0 = fmaf(Dw, m0s[t], warp_excl[t][warp]);
        float M1 = fmaf(Bt, M0, T[t][0]);
        float M2 = fmaf(Bt, M1, T[t][1]);
        float M3 = fmaf(Bt, M2, T[t][2]);
        const float Al = ex2f((float)(lane * 4) * lg2q[t]);
        C0[t][0] = fmaf(Al, M0, E[t][0]);
        C0[t][1] = fmaf(Al, M1, E[t][1]);
        C0[t][2] = fmaf(Al, M2, E[t][2]);
        C0[t][3] = fmaf(Al, M3, E[t][3]);
    }

    const float nalpha = -alpha;

    // ---- phase 4: fused emit — one x load per group, 4 rates interleaved ----
    // scaled recurrence: cy' = xi + q*cy';  u = EPS + s*cy'
    // zp = lg2(fma(xi, e, 1))  -- (1+w) folded into one FMA
    float4* __restrict__ obase = reinterpret_cast<float4*>(out) +
        ((size_t)b * 4 * nbands + f) * NF4;
    const size_t ostride = (size_t)nbands * NF4;     // float4 per rate plane

    #pragma unroll
    for (int i = 0; i < ITERS; i++) {
        const int g = warp * 128 + i * 32 + lane;
        const float4 xi4 = __ldg(xrow4 + g);         // single load per group

        #pragma unroll
        for (int tv = 0; tv < 4; tv++) {
            const float st = s[tv];
            const float qt = q[tv];
            float cy = C0[tv][i];
            float4 o4;
            #pragma unroll
            for (int k = 0; k < 4; k++) {
                const float xi = (&xi4.x)[k];
                cy = fmaf(qt, cy, xi);                              // scaled EMA
                const float u  = fmaf(st, cy, 1e-5f);               // EPS + m
                const float e  = ex2f(fmaf(nalpha, lg2f(u), nl2d)); // sm/d
                const float zp = lg2f(fmaf(xi, e, 1.0f));           // lg2(1+w)
                float p = fmaf(G4, zp, G3);
                p = fmaf(p, zp, G2);
                p = fmaf(p, zp, G1);
                p = fmaf(p, zp, G0);
                (&o4.x)[k] = zp * p;                   // d^r * expm1(r ln(1+w))
            }
            stcs4(obase + (size_t)tv * ostride + g, o4);   // streaming STG.128
        }
    }
}

extern "C" void kernel_launch(void* const* d_in, const int* in_sizes, int n_in,
                              void* d_out, int out_size)
{
    const float* x  = (const float*)d_in[0];
    const float* la = (const float*)d_in[1];
    const float* ld = (const float*)d_in[2];
    const float* lr = (const float*)d_in[3];
    float* out = (float*)d_out;

    const int nbands = in_sizes[1];                 // 128
    const int rows   = in_sizes[0] / N_TIME;        // B * F = 1024

    // s = (sqrt(1 + 4 t^2) - 1) / (2 t^2), computed in double on host
    const double tvals[4] = {2.0, 8.0, 32.0, 128.0};
    float ss[4];
    for (int i = 0; i < 4; i++) {
        double t = tvals[i];
        ss[i] = (float)((sqrt(1.0 + 4.0 * t * t) - 1.0) / (2.0 * t * t));
    }
    float4 sv = make_float4(ss[0], ss[1], ss[2], ss[3]);

    mrpcen_kernel<<<rows, THREADS>>>(x, la, ld, lr, out, sv, nbands);
}